// round 12
// baseline (speedup 1.0000x reference)
#include <cuda_runtime.h>
#include <cuda_fp16.h>
#include <math.h>

#define HH 134
#define WW 20
#define HW 2680
#define CC 64
#define BB 128
#define NTF 8
#define RTF 18
#define NHALO 24         // RTF + 6
#define HSS 480          // NHALO * WW (halfs per channel in smem)

// ---- scratch (static device globals) ----
__device__ float d_psum[NTF * BB * CC];
__device__ float d_pmax[NTF * BB * CC];
__device__ float d_pu[NTF * BB * 8];     // partials of S[k]
__device__ float d_pscA[NTF * BB * 8];
__device__ float d_pscB[NTF * BB * 8];
__device__ int d_cntF[BB], d_cntS[BB], d_cntA[BB], d_cntB[BB];

// per-batch spin barrier (8 blocks per batch)
__device__ __forceinline__ void batch_barrier(int* cnt, int b, int tid) {
    if (tid == 0) {
        __threadfence();
        atomicAdd(&cnt[b], 1);
        while (*((volatile int*)&cnt[b]) < 8) __nanosleep(64);
        __threadfence();
    }
    __syncthreads();
}

// routing update chain (warp 0): sc[16] -> s -> squash -> v -> g
__device__ __forceinline__ void upd_chain(const float* __restrict__ W,
                                          const float* sc, float* vs,
                                          float* g, bool add, int lane) {
    const int j = lane >> 4;
    float acc = 0.f;
#pragma unroll
    for (int k = 0; k < 8; k++) acc += sc[j * 8 + k] * W[k * 32 + lane];
    float s2 = acc * acc;
#pragma unroll
    for (int off = 8; off; off >>= 1) s2 += __shfl_xor_sync(0xffffffffu, s2, off, 16);
    s2 += 1e-8f;
    const float v = (sqrtf(s2) / (1.f + s2)) * acc;
    vs[lane] = v;
    __syncwarp();
    if (lane < 16) {
        const int jj = lane >> 3, k = lane & 7;
        float a = 0.f;
#pragma unroll
        for (int dd = 0; dd < 16; dd++) a += vs[jj * 16 + dd] * W[k * 32 + jj * 16 + dd];
        g[lane] = add ? (g[lane] + a) : a;
    }
    __syncwarp();
}

// ---------------------------------------------------------------------------
// THE kernel: conv + CBAM + capsule routing, fully fused.
// grid (NTF, BB), 256 threads, dyn smem CC*HSS halfs = 60 KB.
// ---------------------------------------------------------------------------
__global__ void k_all(const float* __restrict__ x,
                      const float* __restrict__ cw,
                      const float* __restrict__ cb,
                      const float* __restrict__ sw,
                      const float* __restrict__ w1,
                      const float* __restrict__ w2,
                      const float* __restrict__ W,
                      float* __restrict__ out) {
    extern __shared__ __half hs[];                // [CC][HSS] h, later u
    __shared__ __align__(16) float wsh[CC * 12];
    __shared__ float cbs[CC], cas[CC], ws[98];
    __shared__ float avg_s[CC], mx_s[CC], hid_s[8];
    __shared__ float xs[26 * WW];
    __shared__ float spm[NHALO * WW], spx[NHALO * WW];
    __shared__ float sa_s[RTF * WW];
    __shared__ float red[8][8];
    __shared__ float Ssh[8], ash[8], sc[16], vs[32], g[16];
    __shared__ int lastflag;

    const int tile = blockIdx.x, b = blockIdx.y, tid = threadIdx.x;
    const int warp = tid >> 5, lane = tid & 31;
    const int r0 = tile * RTF, nr = min(RTF, HH - r0);
    const int hs0 = max(r0 - 3, 0), hs1 = min(r0 + nr + 3, HH), nhs = hs1 - hs0;
    const int lx0 = max(hs0 - 1, 0), lx1 = min(hs1 + 1, HH), nlx = lx1 - lx0;

    for (int i = tid; i < CC * 12; i += 256) {
        const int c = i / 12, q = i - c * 12;
        wsh[i] = (q < 9) ? cw[c * 9 + q] : 0.f;
    }
    if (tid < CC) cbs[tid] = cb[tid];
    if (tid >= 64 && tid < 64 + 98) ws[tid - 64] = sw[tid - 64];
    for (int i = tid; i < nlx * WW; i += 256) xs[i] = x[(size_t)b * HW + lx0 * WW + i];
    __syncthreads();

    // ---- stage 1: conv (raw h) over halo rows -> hs ----
    {
        const int pairs = nhs * 10;
        if (tid < pairs) {
            const int lrow = tid / 10, col2 = (tid - lrow * 10) * 2;
            const int row = hs0 + lrow;
            float win[3][4];
#pragma unroll
            for (int r = 0; r < 3; r++) {
                const int ih = row - 1 + r;
                const bool vr = (ih >= lx0) && (ih < lx1);
                const int lr = ih - lx0;
#pragma unroll
                for (int q = 0; q < 4; q++) {
                    const int iw = col2 - 1 + q;
                    win[r][q] = (vr && (unsigned)iw < WW) ? xs[lr * WW + iw] : 0.f;
                }
            }
#pragma unroll 4
            for (int c = 0; c < CC; c++) {
                const float4 wa = *(const float4*)&wsh[c * 12];
                const float4 wb = *(const float4*)&wsh[c * 12 + 4];
                const float w8 = wsh[c * 12 + 8];
                const float bias = cbs[c];
                float h0 = bias + wa.x * win[0][0] + wa.y * win[0][1] + wa.z * win[0][2]
                                + wa.w * win[1][0] + wb.x * win[1][1] + wb.y * win[1][2]
                                + wb.z * win[2][0] + wb.w * win[2][1] + w8 * win[2][2];
                float h1 = bias + wa.x * win[0][1] + wa.y * win[0][2] + wa.z * win[0][3]
                                + wa.w * win[1][1] + wb.x * win[1][2] + wb.y * win[1][3]
                                + wb.z * win[2][1] + wb.w * win[2][2] + w8 * win[2][3];
                *(__half2*)&hs[c * HSS + lrow * WW + col2] =
                    __floats2half2_rn(fmaxf(h0, 0.f), fmaxf(h1, 0.f));
            }
        }
    }
    __syncthreads();

    // ---- stage 2: raw-h stats over OWN rows, partials -> global ----
    {
        const int tot2 = (nr * WW) >> 1;
        const int off2 = ((r0 - hs0) * WW) >> 1;
#pragma unroll
        for (int cc = 0; cc < 8; cc++) {
            const int c = warp * 8 + cc;
            const __half2* hrow = (const __half2*)(hs + c * HSS) + off2;
            float s = 0.f, m = 0.f;
            for (int j = lane; j < tot2; j += 32) {
                const float2 f = __half22float2(hrow[j]);
                s += f.x + f.y;
                m = fmaxf(m, fmaxf(f.x, f.y));
            }
#pragma unroll
            for (int off = 16; off; off >>= 1) {
                s += __shfl_down_sync(0xffffffffu, s, off);
                m = fmaxf(m, __shfl_down_sync(0xffffffffu, m, off));
            }
            if (lane == 0) {
                d_psum[(tile * BB + b) * CC + c] = s;
                d_pmax[(tile * BB + b) * CC + c] = m;
            }
        }
    }
    __syncthreads();

    // ---- stage 3: batch barrier, ca MLP ----
    batch_barrier(d_cntF, b, tid);
    if (tid < CC) {
        float s = 0.f, m = 0.f;
#pragma unroll
        for (int t = 0; t < NTF; t++) {
            s += d_psum[(t * BB + b) * CC + tid];
            m = fmaxf(m, d_pmax[(t * BB + b) * CC + tid]);
        }
        avg_s[tid] = s * (1.f / (float)HW);
        mx_s[tid] = m;
    }
    __syncthreads();
    if (tid < 8) {
        const int i = tid & 3;
        const float* v = (tid < 4) ? avg_s : mx_s;
        float a = 0.f;
        for (int c = 0; c < CC; c++) a += v[c] * w1[i * CC + c];
        hid_s[tid] = fmaxf(a, 0.f);
    }
    __syncthreads();
    if (tid < CC) {
        float o = 0.f;
#pragma unroll
        for (int i = 0; i < 4; i++) o += (hid_s[i] + hid_s[4 + i]) * w2[tid * 4 + i];
        cas[tid] = 1.f / (1.f + __expf(-o));
    }
    __syncthreads();

    // ---- stage 4: spm/spx over halo rows (ca folded) ----
    {
        const int pairs = nhs * 10;
        if (tid < pairs) {
            float s0 = 0.f, s1 = 0.f, m0 = -1e30f, m1 = -1e30f;
#pragma unroll 8
            for (int c = 0; c < CC; c++) {
                const float2 f = __half22float2(*(const __half2*)&hs[c * HSS + tid * 2]);
                const float cv = cas[c];
                const float ax = f.x * cv, ay = f.y * cv;
                s0 += ax; s1 += ay;
                m0 = fmaxf(m0, ax); m1 = fmaxf(m1, ay);
            }
            spm[tid * 2] = s0 * (1.f / (float)CC);
            spm[tid * 2 + 1] = s1 * (1.f / (float)CC);
            spx[tid * 2] = m0;
            spx[tid * 2 + 1] = m1;
        }
    }
    __syncthreads();

    // ---- stage 5: 7x7 -> sa; S partials ----
    float ps[8];
#pragma unroll
    for (int k = 0; k < 8; k++) ps[k] = 0.f;
    for (int p = tid; p < nr * WW; p += 256) {
        const int hh = r0 + p / WW, ww = p - (p / WW) * WW;
        float acc = 0.f;
#pragma unroll
        for (int kh = 0; kh < 7; kh++) {
            const int ih = hh + kh - 3;
            if ((unsigned)ih >= HH) continue;
            const int lrow = ih - hs0;
#pragma unroll
            for (int kw = 0; kw < 7; kw++) {
                const int iw = ww + kw - 3;
                if ((unsigned)iw >= WW) continue;
                const int q = lrow * WW + iw;
                acc += spm[q] * ws[kh * 7 + kw] + spx[q] * ws[49 + kh * 7 + kw];
            }
        }
        const float sa = 1.f / (1.f + __expf(-acc));
        sa_s[p] = sa;
        const int k = (r0 * WW + p) & 7;
        ps[k] += (float)CC * spm[(hh - hs0) * WW + ww] * sa;
    }
#pragma unroll
    for (int k = 0; k < 8; k++) {
#pragma unroll
        for (int off = 16; off; off >>= 1)
            ps[k] += __shfl_down_sync(0xffffffffu, ps[k], off);
    }
    if (lane == 0) {
#pragma unroll
        for (int k = 0; k < 8; k++) red[warp][k] = ps[k];
    }
    __syncthreads();
    if (tid < 8) {
        float s = 0.f;
#pragma unroll
        for (int w = 0; w < 8; w++) s += red[w][tid];
        d_pu[(tile * BB + b) * 8 + tid] = s;
    }

    // ---- stage 6: u = h*ca*sa IN PLACE (own rows only) ----
    {
        const int tot2 = (nr * WW) >> 1;
        const int off2 = ((r0 - hs0) * WW) >> 1;
#pragma unroll
        for (int cc = 0; cc < 8; cc++) {
            const int c = warp * 8 + cc;
            const float cv = cas[c];
            __half2* row = (__half2*)(hs + c * HSS) + off2;
            for (int j = lane; j < tot2; j += 32)
                row[j] = __hmul2(row[j], __floats2half2_rn(cv * sa_s[2 * j],
                                                           cv * sa_s[2 * j + 1]));
        }
    }
    __syncthreads();

    // ---- stage 7: S barrier, g1 ----
    batch_barrier(d_cntS, b, tid);
    if (tid < 32) {
        if (tid < 8) {
            float S = 0.f;
#pragma unroll
            for (int t = 0; t < NTF; t++) S += d_pu[(t * BB + b) * 8 + tid];
            Ssh[tid] = S;
        }
        __syncwarp();
        if (tid < 16) sc[tid] = 0.5f * Ssh[tid & 7];
        __syncwarp();
        upd_chain(W, sc, vs, g, false, tid);
    }
    __syncthreads();

    const int ngroups = (nr * WW) >> 3;      // whole groups per channel (45 or 20)
    const int uoff = (r0 - hs0) * WW;        // half offset of own rows

    float gd[8], a0[8];
    auto smem_pass = [&]() {
#pragma unroll
        for (int k = 0; k < 8; k++) a0[k] = 0.f;
        const int total = CC * ngroups;
        for (int idx = tid; idx < total; idx += 256) {
            const int c = idx / ngroups, gp = idx - c * ngroups;
            const __half* up = hs + c * HSS + uoff + gp * 8;
            const uint2 ra = *(const uint2*)up;
            const uint2 rb = *(const uint2*)(up + 4);
            float u[8];
            float2 f;
            f = __half22float2(*(const __half2*)&ra.x); u[0] = f.x; u[1] = f.y;
            f = __half22float2(*(const __half2*)&ra.y); u[2] = f.x; u[3] = f.y;
            f = __half22float2(*(const __half2*)&rb.x); u[4] = f.x; u[5] = f.y;
            f = __half22float2(*(const __half2*)&rb.y); u[6] = f.x; u[7] = f.y;
            float d = 0.f;
#pragma unroll
            for (int k = 0; k < 8; k++) d += u[k] * gd[k];
            const float c0 = 1.f / (1.f + __expf(-d));
#pragma unroll
            for (int k = 0; k < 8; k++) a0[k] += c0 * u[k];
        }
#pragma unroll
        for (int k = 0; k < 8; k++) {
#pragma unroll
            for (int off = 16; off; off >>= 1)
                a0[k] += __shfl_down_sync(0xffffffffu, a0[k], off);
        }
        if (lane == 0) {
#pragma unroll
            for (int k = 0; k < 8; k++) red[warp][k] = a0[k];
        }
        __syncthreads();
    };

    // ---- pass A ----
#pragma unroll
    for (int k = 0; k < 8; k++) gd[k] = g[k] - g[8 + k];
    smem_pass();
    if (tid < 8) {
        float s = 0.f;
#pragma unroll
        for (int w = 0; w < 8; w++) s += red[w][tid];
        d_pscA[(tile * BB + b) * 8 + tid] = s;
    }
    __syncthreads();
    batch_barrier(d_cntA, b, tid);

    // g2 = g1 + dW(pscA)
    if (tid < 32) {
        if (tid < 8) {
            float a = 0.f;
#pragma unroll
            for (int t = 0; t < NTF; t++) a += d_pscA[(t * BB + b) * 8 + tid];
            ash[tid] = a;
        }
        __syncwarp();
        if (tid < 16) sc[tid] = (tid < 8) ? ash[tid] : (Ssh[tid - 8] - ash[tid - 8]);
        __syncwarp();
        upd_chain(W, sc, vs, g, true, tid);
    }
    __syncthreads();

    // ---- pass B ----
#pragma unroll
    for (int k = 0; k < 8; k++) gd[k] = g[k] - g[8 + k];
    smem_pass();
    if (tid < 8) {
        float s = 0.f;
#pragma unroll
        for (int w = 0; w < 8; w++) s += red[w][tid];
        d_pscB[(tile * BB + b) * 8 + tid] = s;
    }
    __syncthreads();

    // ---- final: last block of batch computes lengths, resets counters ----
    if (tid == 0) {
        __threadfence();
        lastflag = (atomicAdd(&d_cntB[b], 1) == 7) ? 1 : 0;
    }
    __syncthreads();
    if (lastflag) {
        if (tid < 32) {
            __threadfence();
            if (tid < 8) {
                float a = 0.f;
#pragma unroll
                for (int t = 0; t < NTF; t++) a += d_pscB[(t * BB + b) * 8 + tid];
                ash[tid] = a;
            }
            __syncwarp();
            if (tid < 16) sc[tid] = (tid < 8) ? ash[tid] : (Ssh[tid - 8] - ash[tid - 8]);
            __syncwarp();
            const int j = tid >> 4;
            float acc = 0.f;
#pragma unroll
            for (int k = 0; k < 8; k++) acc += sc[j * 8 + k] * W[k * 32 + tid];
            float s2 = acc * acc;
#pragma unroll
            for (int off = 8; off; off >>= 1) s2 += __shfl_xor_sync(0xffffffffu, s2, off, 16);
            s2 += 1e-8f;
            const float v = (sqrtf(s2) / (1.f + s2)) * acc;
            float l2 = v * v;
#pragma unroll
            for (int off = 8; off; off >>= 1) l2 += __shfl_xor_sync(0xffffffffu, l2, off, 16);
            if ((tid & 15) == 0) out[b * 2 + j] = sqrtf(l2 + 1e-8f);
        }
        __syncthreads();
        if (tid == 0) {   // reset per-batch counters for next graph replay
            d_cntF[b] = 0;
            d_cntS[b] = 0;
            d_cntA[b] = 0;
            d_cntB[b] = 0;
        }
    }
}

// ---------------------------------------------------------------------------
extern "C" void kernel_launch(void* const* d_in, const int* in_sizes, int n_in,
                              void* d_out, int out_size) {
    const float* x      = (const float*)d_in[0];
    const float* conv_w = (const float*)d_in[1];
    const float* conv_b = (const float*)d_in[2];
    const float* ca_w1  = (const float*)d_in[3];
    const float* ca_w2  = (const float*)d_in[4];
    const float* sa_w   = (const float*)d_in[5];
    const float* caps_W = (const float*)d_in[6];
    float* out = (float*)d_out;

    const int hs_bytes = CC * HSS * sizeof(__half);   // 61440
    cudaFuncSetAttribute(k_all, cudaFuncAttributeMaxDynamicSharedMemorySize, hs_bytes);

    k_all<<<dim3(NTF, BB), 256, hs_bytes>>>(x, conv_w, conv_b, sa_w,
                                            ca_w1, ca_w2, caps_W, out);
}

// round 13
// speedup vs baseline: 1.0984x; 1.0984x over previous
#include <cuda_runtime.h>
#include <cuda_fp16.h>
#include <cuda_fp8.h>
#include <math.h>

#define HH 134
#define WW 20
#define HW 2680
#define CC 64
#define BB 128
#define NIN 21440        // 8-elem groups per batch
#define NTF 8
#define RTF 17
#define NHALO 23         // RTF + 6
#define HSS 460          // NHALO * WW

// ---- scratch (static device globals) ----
__device__ unsigned char d_u[(size_t)BB * CC * HW];  // u fp8 e4m3, 22 MB
__device__ float d_psum[NTF * BB * CC];
__device__ float d_pmax[NTF * BB * CC];
__device__ float d_pu[NTF * BB * 8];
__device__ float d_pscA[8 * BB * 8];
__device__ float d_pscB[8 * BB * 8];
__device__ int d_cntF[BB];   // fuse stats barrier
__device__ int d_cntU[BB];   // fuse-complete marker (awaited by route)
__device__ int d_cntA[BB];   // route pass-A barrier
__device__ int d_cntB[BB];   // route pass-B / final

// per-batch spin barrier among 8 peer blocks
__device__ __forceinline__ void batch_barrier(int* cnt, int b, int tid) {
    if (tid == 0) {
        __threadfence();
        atomicAdd(&cnt[b], 1);
        while (*((volatile int*)&cnt[b]) < 8) __nanosleep(64);
        __threadfence();
    }
    __syncthreads();
}
// wait-only (consumer side)
__device__ __forceinline__ void batch_wait(int* cnt, int b, int tid) {
    if (tid == 0) {
        while (*((volatile int*)&cnt[b]) < 8) __nanosleep(64);
        __threadfence();
    }
    __syncthreads();
}

// routing update chain (warp 0): sc[16] -> s -> squash -> v -> g
__device__ __forceinline__ void upd_chain(const float* __restrict__ W,
                                          const float* sc, float* vs,
                                          float* g, bool add, int lane) {
    const int j = lane >> 4;
    float acc = 0.f;
#pragma unroll
    for (int k = 0; k < 8; k++) acc += sc[j * 8 + k] * W[k * 32 + lane];
    float s2 = acc * acc;
#pragma unroll
    for (int off = 8; off; off >>= 1) s2 += __shfl_xor_sync(0xffffffffu, s2, off, 16);
    s2 += 1e-8f;
    const float v = (sqrtf(s2) / (1.f + s2)) * acc;
    vs[lane] = v;
    __syncwarp();
    if (lane < 16) {
        const int jj = lane >> 3, k = lane & 7;
        float a = 0.f;
#pragma unroll
        for (int dd = 0; dd < 16; dd++) a += vs[jj * 16 + dd] * W[k * 32 + jj * 16 + dd];
        g[lane] = add ? (g[lane] + a) : a;
    }
    __syncwarp();
}

// ---------------------------------------------------------------------------
// ONE kernel, two roles. grid (16, BB): x<8 fuse tile, x>=8 route chunk.
// Dispatch order interleaves fuse(b) before route(b) -> per-batch pipelining.
// ---------------------------------------------------------------------------
__global__ void __launch_bounds__(256, 2)
k_mega(const float* __restrict__ x,
       const float* __restrict__ cw,
       const float* __restrict__ cb,
       const float* __restrict__ sw,
       const float* __restrict__ w1,
       const float* __restrict__ w2,
       const float* __restrict__ W,
       float* __restrict__ out) {
    extern __shared__ __half hs[];                // fuse: [CC][HSS] h fp16
    __shared__ __align__(16) float wsh[CC * 12];
    __shared__ float cbs[CC], cas[CC], ws[98];
    __shared__ float avg_s[CC], mx_s[CC], hid_s[8];
    __shared__ float xs[25 * WW];
    __shared__ float spm[NHALO * WW], spx[NHALO * WW];
    __shared__ float sa_s[RTF * WW];
    __shared__ float red[8][8];
    __shared__ float Ssh[8], ash[8], sc[16], vs[32], g[16];
    __shared__ int lastflag;

    const int b = blockIdx.y, tid = threadIdx.x;
    const int warp = tid >> 5, lane = tid & 31;

    if (blockIdx.x < 8) {
        // =================== FUSE ROLE (round-11 k_fuse_all) ===================
        const int tile = blockIdx.x;
        const int r0 = tile * RTF, nr = min(RTF, HH - r0);
        const int hs0 = max(r0 - 3, 0), hs1 = min(r0 + nr + 3, HH), nhs = hs1 - hs0;
        const int lx0 = max(hs0 - 1, 0), lx1 = min(hs1 + 1, HH), nlx = lx1 - lx0;

        for (int i = tid; i < CC * 12; i += 256) {
            const int c = i / 12, q = i - c * 12;
            wsh[i] = (q < 9) ? cw[c * 9 + q] : 0.f;
        }
        if (tid < CC) cbs[tid] = cb[tid];
        if (tid >= 64 && tid < 64 + 98) ws[tid - 64] = sw[tid - 64];
        for (int i = tid; i < nlx * WW; i += 256) xs[i] = x[(size_t)b * HW + lx0 * WW + i];
        __syncthreads();

        // stage 1: conv raw h over halo rows -> hs
        {
            const int pairs = nhs * 10;
            if (tid < pairs) {
                const int lrow = tid / 10, col2 = (tid - lrow * 10) * 2;
                const int row = hs0 + lrow;
                float win[3][4];
#pragma unroll
                for (int r = 0; r < 3; r++) {
                    const int ih = row - 1 + r;
                    const bool vr = (ih >= lx0) && (ih < lx1);
                    const int lr = ih - lx0;
#pragma unroll
                    for (int q = 0; q < 4; q++) {
                        const int iw = col2 - 1 + q;
                        win[r][q] = (vr && (unsigned)iw < WW) ? xs[lr * WW + iw] : 0.f;
                    }
                }
#pragma unroll 4
                for (int c = 0; c < CC; c++) {
                    const float4 wa = *(const float4*)&wsh[c * 12];
                    const float4 wb = *(const float4*)&wsh[c * 12 + 4];
                    const float w8 = wsh[c * 12 + 8];
                    const float bias = cbs[c];
                    float h0 = bias + wa.x * win[0][0] + wa.y * win[0][1] + wa.z * win[0][2]
                                    + wa.w * win[1][0] + wb.x * win[1][1] + wb.y * win[1][2]
                                    + wb.z * win[2][0] + wb.w * win[2][1] + w8 * win[2][2];
                    float h1 = bias + wa.x * win[0][1] + wa.y * win[0][2] + wa.z * win[0][3]
                                    + wa.w * win[1][1] + wb.x * win[1][2] + wb.y * win[1][3]
                                    + wb.z * win[2][1] + wb.w * win[2][2] + w8 * win[2][3];
                    *(__half2*)&hs[c * HSS + lrow * WW + col2] =
                        __floats2half2_rn(fmaxf(h0, 0.f), fmaxf(h1, 0.f));
                }
            }
        }
        __syncthreads();

        // stage 2: raw-h stats over OWN rows -> partials
        {
            const int tot2 = (nr * WW) >> 1;
            const int off2 = ((r0 - hs0) * WW) >> 1;
#pragma unroll
            for (int cc = 0; cc < 8; cc++) {
                const int c = warp * 8 + cc;
                const __half2* hrow = (const __half2*)(hs + c * HSS) + off2;
                float s = 0.f, m = 0.f;
                for (int j = lane; j < tot2; j += 32) {
                    const float2 f = __half22float2(hrow[j]);
                    s += f.x + f.y;
                    m = fmaxf(m, fmaxf(f.x, f.y));
                }
#pragma unroll
                for (int off = 16; off; off >>= 1) {
                    s += __shfl_down_sync(0xffffffffu, s, off);
                    m = fmaxf(m, __shfl_down_sync(0xffffffffu, m, off));
                }
                if (lane == 0) {
                    d_psum[(tile * BB + b) * CC + c] = s;
                    d_pmax[(tile * BB + b) * CC + c] = m;
                }
            }
        }
        __syncthreads();

        // stage 3: batch barrier + ca MLP
        batch_barrier(d_cntF, b, tid);
        if (tid < CC) {
            float s = 0.f, m = 0.f;
#pragma unroll
            for (int t = 0; t < NTF; t++) {
                s += d_psum[(t * BB + b) * CC + tid];
                m = fmaxf(m, d_pmax[(t * BB + b) * CC + tid]);
            }
            avg_s[tid] = s * (1.f / (float)HW);
            mx_s[tid] = m;
        }
        __syncthreads();
        if (tid < 8) {
            const int i = tid & 3;
            const float* v = (tid < 4) ? avg_s : mx_s;
            float a = 0.f;
            for (int c = 0; c < CC; c++) a += v[c] * w1[i * CC + c];
            hid_s[tid] = fmaxf(a, 0.f);
        }
        __syncthreads();
        if (tid < CC) {
            float o = 0.f;
#pragma unroll
            for (int i = 0; i < 4; i++) o += (hid_s[i] + hid_s[4 + i]) * w2[tid * 4 + i];
            cas[tid] = 1.f / (1.f + __expf(-o));
        }
        __syncthreads();

        // stage 4: spm/spx over halo rows (ca folded)
        {
            const int pairs = nhs * 10;
            if (tid < pairs) {
                float s0 = 0.f, s1 = 0.f, m0 = -1e30f, m1 = -1e30f;
#pragma unroll 8
                for (int c = 0; c < CC; c++) {
                    const float2 f = __half22float2(*(const __half2*)&hs[c * HSS + tid * 2]);
                    const float cv = cas[c];
                    const float ax = f.x * cv, ay = f.y * cv;
                    s0 += ax; s1 += ay;
                    m0 = fmaxf(m0, ax); m1 = fmaxf(m1, ay);
                }
                spm[tid * 2] = s0 * (1.f / (float)CC);
                spm[tid * 2 + 1] = s1 * (1.f / (float)CC);
                spx[tid * 2] = m0;
                spx[tid * 2 + 1] = m1;
            }
        }
        __syncthreads();

        // stage 5: 7x7 -> sa; S partials
        float ps[8];
#pragma unroll
        for (int k = 0; k < 8; k++) ps[k] = 0.f;
        for (int p = tid; p < nr * WW; p += 256) {
            const int hh = r0 + p / WW, ww = p - (p / WW) * WW;
            float acc = 0.f;
#pragma unroll
            for (int kh = 0; kh < 7; kh++) {
                const int ih = hh + kh - 3;
                if ((unsigned)ih >= HH) continue;
                const int lrow = ih - hs0;
#pragma unroll
                for (int kw = 0; kw < 7; kw++) {
                    const int iw = ww + kw - 3;
                    if ((unsigned)iw >= WW) continue;
                    const int q = lrow * WW + iw;
                    acc += spm[q] * ws[kh * 7 + kw] + spx[q] * ws[49 + kh * 7 + kw];
                }
            }
            const float sa = 1.f / (1.f + __expf(-acc));
            sa_s[p] = sa;
            const int k = (r0 * WW + p) & 7;
            ps[k] += (float)CC * spm[(hh - hs0) * WW + ww] * sa;
        }
#pragma unroll
        for (int k = 0; k < 8; k++) {
#pragma unroll
            for (int off = 16; off; off >>= 1)
                ps[k] += __shfl_down_sync(0xffffffffu, ps[k], off);
        }
        if (lane == 0) {
#pragma unroll
            for (int k = 0; k < 8; k++) red[warp][k] = ps[k];
        }
        __syncthreads();
        if (tid < 8) {
            float s = 0.f;
#pragma unroll
            for (int w = 0; w < 8; w++) s += red[w][tid];
            d_pu[(tile * BB + b) * 8 + tid] = s;
        }

        // stage 6: u = h*ca*sa -> fp8 global, warp-per-channel coalesced
        {
            const int tot4 = (nr * WW) >> 2;
            const int off2 = ((r0 - hs0) * WW) >> 1;
#pragma unroll
            for (int cc = 0; cc < 8; cc++) {
                const int c = warp * 8 + cc;
                const float cv = cas[c];
                const __half2* hrow = (const __half2*)(hs + c * HSS) + off2;
                unsigned* urow = (unsigned*)(d_u + (size_t)(b * CC + c) * HW + r0 * WW);
                for (int j = lane; j < tot4; j += 32) {
                    const float2 fa = __half22float2(hrow[2 * j]);
                    const float2 fb = __half22float2(hrow[2 * j + 1]);
                    float2 q0, q1;
                    q0.x = fa.x * (cv * sa_s[4 * j]);
                    q0.y = fa.y * (cv * sa_s[4 * j + 1]);
                    q1.x = fb.x * (cv * sa_s[4 * j + 2]);
                    q1.y = fb.y * (cv * sa_s[4 * j + 3]);
                    const unsigned lo = __nv_cvt_float2_to_fp8x2(q0, __NV_SATFINITE, __NV_E4M3);
                    const unsigned hi = __nv_cvt_float2_to_fp8x2(q1, __NV_SATFINITE, __NV_E4M3);
                    urow[j] = (hi << 16) | lo;
                }
            }
        }
        __syncthreads();
        if (tid == 0) {   // mark this tile's u + partials complete
            __threadfence();
            atomicAdd(&d_cntU[b], 1);
        }
        return;
    }

    // =================== ROUTE ROLE (round-11 k_route_all) ===================
    const int chunk = blockIdx.x - 8;

    // wait for this batch's fuse blocks
    batch_wait(d_cntU, b, tid);

    // g1 from S
    if (tid < 32) {
        if (tid < 8) {
            float S = 0.f;
#pragma unroll
            for (int t = 0; t < NTF; t++) S += d_pu[(t * BB + b) * 8 + tid];
            Ssh[tid] = S;
        }
        __syncwarp();
        if (tid < 16) sc[tid] = 0.5f * Ssh[tid & 7];
        __syncwarp();
        upd_chain(W, sc, vs, g, false, tid);
    }
    __syncthreads();

    const uint4* up4 = (const uint4*)(d_u + (size_t)b * CC * HW + (size_t)chunk * (NIN / 8) * 8);
    const int npair = NIN / 16;

    float gd[8], a0[8];
    auto stream_pass = [&]() {
#pragma unroll
        for (int k = 0; k < 8; k++) a0[k] = 0.f;
        auto comp = [&](const uint4& raw) {
            const unsigned v[4] = {raw.x, raw.y, raw.z, raw.w};
            float u[16];
#pragma unroll
            for (int q = 0; q < 4; q++) {
                const __half2_raw hr0 = __nv_cvt_fp8x2_to_halfraw2(
                    (__nv_fp8x2_storage_t)(v[q] & 0xffffu), __NV_E4M3);
                const __half2_raw hr1 = __nv_cvt_fp8x2_to_halfraw2(
                    (__nv_fp8x2_storage_t)(v[q] >> 16), __NV_E4M3);
                const float2 f0 = __half22float2(__half2(hr0));
                const float2 f1 = __half22float2(__half2(hr1));
                u[q * 4 + 0] = f0.x; u[q * 4 + 1] = f0.y;
                u[q * 4 + 2] = f1.x; u[q * 4 + 3] = f1.y;
            }
            float d0 = 0.f, d1 = 0.f;
#pragma unroll
            for (int k = 0; k < 8; k++) { d0 += u[k] * gd[k]; d1 += u[8 + k] * gd[k]; }
            const float c0a = 1.f / (1.f + __expf(-d0));
            const float c0b = 1.f / (1.f + __expf(-d1));
#pragma unroll
            for (int k = 0; k < 8; k++) a0[k] += c0a * u[k] + c0b * u[8 + k];
        };
        int i = tid;
        for (; i + 768 < npair; i += 1024) {
            const uint4 r0 = up4[i];
            const uint4 r1 = up4[i + 256];
            const uint4 r2 = up4[i + 512];
            const uint4 r3 = up4[i + 768];
            comp(r0); comp(r1); comp(r2); comp(r3);
        }
        for (; i < npair; i += 256) {
            const uint4 r0 = up4[i];
            comp(r0);
        }
#pragma unroll
        for (int k = 0; k < 8; k++) {
#pragma unroll
            for (int off = 16; off; off >>= 1)
                a0[k] += __shfl_down_sync(0xffffffffu, a0[k], off);
        }
        if (lane == 0) {
#pragma unroll
            for (int k = 0; k < 8; k++) red[warp][k] = a0[k];
        }
        __syncthreads();
    };

    // pass A
#pragma unroll
    for (int k = 0; k < 8; k++) gd[k] = g[k] - g[8 + k];
    stream_pass();
    if (tid < 8) {
        float s = 0.f;
#pragma unroll
        for (int w = 0; w < 8; w++) s += red[w][tid];
        d_pscA[(chunk * BB + b) * 8 + tid] = s;
    }
    __syncthreads();
    batch_barrier(d_cntA, b, tid);

    // g2 = g1 + dW(pscA)
    if (tid < 32) {
        if (tid < 8) {
            float a = 0.f;
#pragma unroll
            for (int ch = 0; ch < 8; ch++) a += d_pscA[(ch * BB + b) * 8 + tid];
            ash[tid] = a;
        }
        __syncwarp();
        if (tid < 16) sc[tid] = (tid < 8) ? ash[tid] : (Ssh[tid - 8] - ash[tid - 8]);
        __syncwarp();
        upd_chain(W, sc, vs, g, true, tid);
    }
    __syncthreads();

    // pass B
#pragma unroll
    for (int k = 0; k < 8; k++) gd[k] = g[k] - g[8 + k];
    stream_pass();
    if (tid < 8) {
        float s = 0.f;
#pragma unroll
        for (int w = 0; w < 8; w++) s += red[w][tid];
        d_pscB[(chunk * BB + b) * 8 + tid] = s;
    }
    __syncthreads();

    // final: last route block of batch computes lengths + resets counters
    if (tid == 0) {
        __threadfence();
        lastflag = (atomicAdd(&d_cntB[b], 1) == 7) ? 1 : 0;
    }
    __syncthreads();
    if (lastflag) {
        if (tid < 32) {
            __threadfence();
            if (tid < 8) {
                float a = 0.f;
#pragma unroll
                for (int ch = 0; ch < 8; ch++) a += d_pscB[(ch * BB + b) * 8 + tid];
                ash[tid] = a;
            }
            __syncwarp();
            if (tid < 16) sc[tid] = (tid < 8) ? ash[tid] : (Ssh[tid - 8] - ash[tid - 8]);
            __syncwarp();
            const int j = tid >> 4;
            float acc = 0.f;
#pragma unroll
            for (int k = 0; k < 8; k++) acc += sc[j * 8 + k] * W[k * 32 + tid];
            float s2 = acc * acc;
#pragma unroll
            for (int off = 8; off; off >>= 1) s2 += __shfl_xor_sync(0xffffffffu, s2, off, 16);
            s2 += 1e-8f;
            const float v = (sqrtf(s2) / (1.f + s2)) * acc;
            float l2 = v * v;
#pragma unroll
            for (int off = 8; off; off >>= 1) l2 += __shfl_xor_sync(0xffffffffu, l2, off, 16);
            if ((tid & 15) == 0) out[b * 2 + j] = sqrtf(l2 + 1e-8f);
        }
        __syncthreads();
        if (tid == 0) {   // reset per-batch counters for next graph replay
            d_cntF[b] = 0;
            d_cntU[b] = 0;
            d_cntA[b] = 0;
            d_cntB[b] = 0;
        }
    }
}

// ---------------------------------------------------------------------------
extern "C" void kernel_launch(void* const* d_in, const int* in_sizes, int n_in,
                              void* d_out, int out_size) {
    const float* x      = (const float*)d_in[0];
    const float* conv_w = (const float*)d_in[1];
    const float* conv_b = (const float*)d_in[2];
    const float* ca_w1  = (const float*)d_in[3];
    const float* ca_w2  = (const float*)d_in[4];
    const float* sa_w   = (const float*)d_in[5];
    const float* caps_W = (const float*)d_in[6];
    float* out = (float*)d_out;

    const int hs_bytes = CC * HSS * sizeof(__half);   // 58880
    cudaFuncSetAttribute(k_mega, cudaFuncAttributeMaxDynamicSharedMemorySize, hs_bytes);

    k_mega<<<dim3(16, BB), 256, hs_bytes>>>(x, conv_w, conv_b, sa_w,
                                            ca_w1, ca_w2, caps_W, out);
}

// round 15
// speedup vs baseline: 1.6491x; 1.5014x over previous
#include <cuda_runtime.h>
#include <cuda_fp16.h>
#include <math.h>

#define HH 134
#define WW 20
#define HW 2680
#define CC 64
#define BB 128
#define NTF 8
#define RTF 18
#define NHALO 24         // RTF + 6
#define HSS 480          // NHALO * WW (halfs per channel in smem)

// ---- scratch (static device globals) ----
__device__ float d_psum[NTF * BB * CC];
__device__ float d_pmax[NTF * BB * CC];
__device__ float d_pu[NTF * BB * 8];     // partials of S[k]
__device__ float d_pscA[NTF * BB * 8];
__device__ float d_pscB[NTF * BB * 8];
__device__ int d_cntF[BB], d_cntS[BB], d_cntA[BB], d_cntB[BB];

// per-batch spin barrier (8 blocks per batch)
__device__ __forceinline__ void batch_barrier(int* cnt, int b, int tid) {
    if (tid == 0) {
        __threadfence();
        atomicAdd(&cnt[b], 1);
        while (*((volatile int*)&cnt[b]) < 8) __nanosleep(64);
        __threadfence();
    }
    __syncthreads();
}

// routing update chain (warp 0): sc[16] -> s -> squash -> v -> g
__device__ __forceinline__ void upd_chain(const float* __restrict__ W,
                                          const float* sc, float* vs,
                                          float* g, bool add, int lane) {
    const int j = lane >> 4;
    float acc = 0.f;
#pragma unroll
    for (int k = 0; k < 8; k++) acc += sc[j * 8 + k] * W[k * 32 + lane];
    float s2 = acc * acc;
#pragma unroll
    for (int off = 8; off; off >>= 1) s2 += __shfl_xor_sync(0xffffffffu, s2, off, 16);
    s2 += 1e-8f;
    const float v = (sqrtf(s2) / (1.f + s2)) * acc;
    vs[lane] = v;
    __syncwarp();
    if (lane < 16) {
        const int jj = lane >> 3, k = lane & 7;
        float a = 0.f;
#pragma unroll
        for (int dd = 0; dd < 16; dd++) a += vs[jj * 16 + dd] * W[k * 32 + jj * 16 + dd];
        g[lane] = add ? (g[lane] + a) : a;
    }
    __syncwarp();
}

// ---------------------------------------------------------------------------
// THE kernel: conv + CBAM + capsule routing, fully fused, smem-resident u.
// grid (NTF, BB), 256 threads, dyn smem CC*HSS halfs = 60 KB.
// __launch_bounds__(256,3): cap regs at 85 so 3 blocks/SM (matches smem cap).
// ---------------------------------------------------------------------------
__global__ void __launch_bounds__(256, 3)
k_all(const float* __restrict__ x,
      const float* __restrict__ cw,
      const float* __restrict__ cb,
      const float* __restrict__ sw,
      const float* __restrict__ w1,
      const float* __restrict__ w2,
      const float* __restrict__ W,
      float* __restrict__ out) {
    extern __shared__ __half hs[];                // [CC][HSS] h, later u
    __shared__ __align__(16) float wsh[CC * 12];
    __shared__ float cbs[CC], cas[CC], ws[98];
    __shared__ float avg_s[CC], mx_s[CC], hid_s[8];
    __shared__ float xs[26 * WW];
    __shared__ float spm[NHALO * WW], spx[NHALO * WW];
    __shared__ float sa_s[RTF * WW];
    __shared__ float red[8][8];
    __shared__ float Ssh[8], ash[8], sc[16], vs[32], g[16];
    __shared__ int lastflag;

    const int tile = blockIdx.x, b = blockIdx.y, tid = threadIdx.x;
    const int warp = tid >> 5, lane = tid & 31;
    const int r0 = tile * RTF, nr = min(RTF, HH - r0);
    const int hs0 = max(r0 - 3, 0), hs1 = min(r0 + nr + 3, HH), nhs = hs1 - hs0;
    const int lx0 = max(hs0 - 1, 0), lx1 = min(hs1 + 1, HH), nlx = lx1 - lx0;

    for (int i = tid; i < CC * 12; i += 256) {
        const int c = i / 12, q = i - c * 12;
        wsh[i] = (q < 9) ? cw[c * 9 + q] : 0.f;
    }
    if (tid < CC) cbs[tid] = cb[tid];
    if (tid >= 64 && tid < 64 + 98) ws[tid - 64] = sw[tid - 64];
    for (int i = tid; i < nlx * WW; i += 256) xs[i] = x[(size_t)b * HW + lx0 * WW + i];
    __syncthreads();

    // ---- stage 1: conv (raw h) over halo rows -> hs ----
    {
        const int pairs = nhs * 10;
        if (tid < pairs) {
            const int lrow = tid / 10, col2 = (tid - lrow * 10) * 2;
            const int row = hs0 + lrow;
            float win[3][4];
#pragma unroll
            for (int r = 0; r < 3; r++) {
                const int ih = row - 1 + r;
                const bool vr = (ih >= lx0) && (ih < lx1);
                const int lr = ih - lx0;
#pragma unroll
                for (int q = 0; q < 4; q++) {
                    const int iw = col2 - 1 + q;
                    win[r][q] = (vr && (unsigned)iw < WW) ? xs[lr * WW + iw] : 0.f;
                }
            }
#pragma unroll 2
            for (int c = 0; c < CC; c++) {
                const float4 wa = *(const float4*)&wsh[c * 12];
                const float4 wb = *(const float4*)&wsh[c * 12 + 4];
                const float w8 = wsh[c * 12 + 8];
                const float bias = cbs[c];
                float h0 = bias + wa.x * win[0][0] + wa.y * win[0][1] + wa.z * win[0][2]
                                + wa.w * win[1][0] + wb.x * win[1][1] + wb.y * win[1][2]
                                + wb.z * win[2][0] + wb.w * win[2][1] + w8 * win[2][2];
                float h1 = bias + wa.x * win[0][1] + wa.y * win[0][2] + wa.z * win[0][3]
                                + wa.w * win[1][1] + wb.x * win[1][2] + wb.y * win[1][3]
                                + wb.z * win[2][1] + wb.w * win[2][2] + w8 * win[2][3];
                *(__half2*)&hs[c * HSS + lrow * WW + col2] =
                    __floats2half2_rn(fmaxf(h0, 0.f), fmaxf(h1, 0.f));
            }
        }
    }
    __syncthreads();

    // ---- stage 2: raw-h stats over OWN rows, partials -> global ----
    {
        const int tot2 = (nr * WW) >> 1;
        const int off2 = ((r0 - hs0) * WW) >> 1;
#pragma unroll
        for (int cc = 0; cc < 8; cc++) {
            const int c = warp * 8 + cc;
            const __half2* hrow = (const __half2*)(hs + c * HSS) + off2;
            float s = 0.f, m = 0.f;
            for (int j = lane; j < tot2; j += 32) {
                const float2 f = __half22float2(hrow[j]);
                s += f.x + f.y;
                m = fmaxf(m, fmaxf(f.x, f.y));
            }
#pragma unroll
            for (int off = 16; off; off >>= 1) {
                s += __shfl_down_sync(0xffffffffu, s, off);
                m = fmaxf(m, __shfl_down_sync(0xffffffffu, m, off));
            }
            if (lane == 0) {
                d_psum[(tile * BB + b) * CC + c] = s;
                d_pmax[(tile * BB + b) * CC + c] = m;
            }
        }
    }
    __syncthreads();

    // ---- stage 3: batch barrier, ca MLP ----
    batch_barrier(d_cntF, b, tid);
    if (tid < CC) {
        float s = 0.f, m = 0.f;
#pragma unroll
        for (int t = 0; t < NTF; t++) {
            s += d_psum[(t * BB + b) * CC + tid];
            m = fmaxf(m, d_pmax[(t * BB + b) * CC + tid]);
        }
        avg_s[tid] = s * (1.f / (float)HW);
        mx_s[tid] = m;
    }
    __syncthreads();
    if (tid < 8) {
        const int i = tid & 3;
        const float* v = (tid < 4) ? avg_s : mx_s;
        float a = 0.f;
        for (int c = 0; c < CC; c++) a += v[c] * w1[i * CC + c];
        hid_s[tid] = fmaxf(a, 0.f);
    }
    __syncthreads();
    if (tid < CC) {
        float o = 0.f;
#pragma unroll
        for (int i = 0; i < 4; i++) o += (hid_s[i] + hid_s[4 + i]) * w2[tid * 4 + i];
        cas[tid] = 1.f / (1.f + __expf(-o));
    }
    __syncthreads();

    // ---- stage 4: spm/spx over halo rows (ca folded) ----
    {
        const int pairs = nhs * 10;
        if (tid < pairs) {
            float s0 = 0.f, s1 = 0.f, m0 = -1e30f, m1 = -1e30f;
#pragma unroll 8
            for (int c = 0; c < CC; c++) {
                const float2 f = __half22float2(*(const __half2*)&hs[c * HSS + tid * 2]);
                const float cv = cas[c];
                const float ax = f.x * cv, ay = f.y * cv;
                s0 += ax; s1 += ay;
                m0 = fmaxf(m0, ax); m1 = fmaxf(m1, ay);
            }
            spm[tid * 2] = s0 * (1.f / (float)CC);
            spm[tid * 2 + 1] = s1 * (1.f / (float)CC);
            spx[tid * 2] = m0;
            spx[tid * 2 + 1] = m1;
        }
    }
    __syncthreads();

    // ---- stage 5: 7x7 -> sa; S partials ----
    float ps[8];
#pragma unroll
    for (int k = 0; k < 8; k++) ps[k] = 0.f;
    for (int p = tid; p < nr * WW; p += 256) {
        const int hh = r0 + p / WW, ww = p - (p / WW) * WW;
        float acc = 0.f;
#pragma unroll
        for (int kh = 0; kh < 7; kh++) {
            const int ih = hh + kh - 3;
            if ((unsigned)ih >= HH) continue;
            const int lrow = ih - hs0;
#pragma unroll
            for (int kw = 0; kw < 7; kw++) {
                const int iw = ww + kw - 3;
                if ((unsigned)iw >= WW) continue;
                const int q = lrow * WW + iw;
                acc += spm[q] * ws[kh * 7 + kw] + spx[q] * ws[49 + kh * 7 + kw];
            }
        }
        const float sa = 1.f / (1.f + __expf(-acc));
        sa_s[p] = sa;
        const int k = (r0 * WW + p) & 7;
        ps[k] += (float)CC * spm[(hh - hs0) * WW + ww] * sa;
    }
#pragma unroll
    for (int k = 0; k < 8; k++) {
#pragma unroll
        for (int off = 16; off; off >>= 1)
            ps[k] += __shfl_down_sync(0xffffffffu, ps[k], off);
    }
    if (lane == 0) {
#pragma unroll
        for (int k = 0; k < 8; k++) red[warp][k] = ps[k];
    }
    __syncthreads();
    if (tid < 8) {
        float s = 0.f;
#pragma unroll
        for (int w = 0; w < 8; w++) s += red[w][tid];
        d_pu[(tile * BB + b) * 8 + tid] = s;
    }

    // ---- stage 6: u = h*ca*sa IN PLACE (own rows only) ----
    {
        const int tot2 = (nr * WW) >> 1;
        const int off2 = ((r0 - hs0) * WW) >> 1;
#pragma unroll
        for (int cc = 0; cc < 8; cc++) {
            const int c = warp * 8 + cc;
            const float cv = cas[c];
            __half2* row = (__half2*)(hs + c * HSS) + off2;
            for (int j = lane; j < tot2; j += 32)
                row[j] = __hmul2(row[j], __floats2half2_rn(cv * sa_s[2 * j],
                                                           cv * sa_s[2 * j + 1]));
        }
    }
    __syncthreads();

    // ---- stage 7: S barrier, g1 ----
    batch_barrier(d_cntS, b, tid);
    if (tid < 32) {
        if (tid < 8) {
            float S = 0.f;
#pragma unroll
            for (int t = 0; t < NTF; t++) S += d_pu[(t * BB + b) * 8 + tid];
            Ssh[tid] = S;
        }
        __syncwarp();
        if (tid < 16) sc[tid] = 0.5f * Ssh[tid & 7];
        __syncwarp();
        upd_chain(W, sc, vs, g, false, tid);
    }
    __syncthreads();

    const int ngroups = (nr * WW) >> 3;      // whole groups per channel
    const int uoff = (r0 - hs0) * WW;        // half offset of own rows

    float gd[8], a0[8];
    auto smem_pass = [&]() {
#pragma unroll
        for (int k = 0; k < 8; k++) a0[k] = 0.f;
        const int total = CC * ngroups;
        for (int idx = tid; idx < total; idx += 256) {
            const int c = idx / ngroups, gp = idx - c * ngroups;
            const __half* up = hs + c * HSS + uoff + gp * 8;
            const uint2 ra = *(const uint2*)up;
            const uint2 rb = *(const uint2*)(up + 4);
            float u[8];
            float2 f;
            f = __half22float2(*(const __half2*)&ra.x); u[0] = f.x; u[1] = f.y;
            f = __half22float2(*(const __half2*)&ra.y); u[2] = f.x; u[3] = f.y;
            f = __half22float2(*(const __half2*)&rb.x); u[4] = f.x; u[5] = f.y;
            f = __half22float2(*(const __half2*)&rb.y); u[6] = f.x; u[7] = f.y;
            float d = 0.f;
#pragma unroll
            for (int k = 0; k < 8; k++) d += u[k] * gd[k];
            const float c0 = 1.f / (1.f + __expf(-d));
#pragma unroll
            for (int k = 0; k < 8; k++) a0[k] += c0 * u[k];
        }
#pragma unroll
        for (int k = 0; k < 8; k++) {
#pragma unroll
            for (int off = 16; off; off >>= 1)
                a0[k] += __shfl_down_sync(0xffffffffu, a0[k], off);
        }
        if (lane == 0) {
#pragma unroll
            for (int k = 0; k < 8; k++) red[warp][k] = a0[k];
        }
        __syncthreads();
    };

    // ---- pass A ----
#pragma unroll
    for (int k = 0; k < 8; k++) gd[k] = g[k] - g[8 + k];
    smem_pass();
    if (tid < 8) {
        float s = 0.f;
#pragma unroll
        for (int w = 0; w < 8; w++) s += red[w][tid];
        d_pscA[(tile * BB + b) * 8 + tid] = s;
    }
    __syncthreads();
    batch_barrier(d_cntA, b, tid);

    // g2 = g1 + dW(pscA)
    if (tid < 32) {
        if (tid < 8) {
            float a = 0.f;
#pragma unroll
            for (int t = 0; t < NTF; t++) a += d_pscA[(t * BB + b) * 8 + tid];
            ash[tid] = a;
        }
        __syncwarp();
        if (tid < 16) sc[tid] = (tid < 8) ? ash[tid] : (Ssh[tid - 8] - ash[tid - 8]);
        __syncwarp();
        upd_chain(W, sc, vs, g, true, tid);
    }
    __syncthreads();

    // ---- pass B ----
#pragma unroll
    for (int k = 0; k < 8; k++) gd[k] = g[k] - g[8 + k];
    smem_pass();
    if (tid < 8) {
        float s = 0.f;
#pragma unroll
        for (int w = 0; w < 8; w++) s += red[w][tid];
        d_pscB[(tile * BB + b) * 8 + tid] = s;
    }
    __syncthreads();

    // ---- final: last block of batch computes lengths, resets counters ----
    if (tid == 0) {
        __threadfence();
        lastflag = (atomicAdd(&d_cntB[b], 1) == 7) ? 1 : 0;
    }
    __syncthreads();
    if (lastflag) {
        if (tid < 32) {
            __threadfence();
            if (tid < 8) {
                float a = 0.f;
#pragma unroll
                for (int t = 0; t < NTF; t++) a += d_pscB[(t * BB + b) * 8 + tid];
                ash[tid] = a;
            }
            __syncwarp();
            if (tid < 16) sc[tid] = (tid < 8) ? ash[tid] : (Ssh[tid - 8] - ash[tid - 8]);
            __syncwarp();
            const int j = tid >> 4;
            float acc = 0.f;
#pragma unroll
            for (int k = 0; k < 8; k++) acc += sc[j * 8 + k] * W[k * 32 + tid];
            float s2 = acc * acc;
#pragma unroll
            for (int off = 8; off; off >>= 1) s2 += __shfl_xor_sync(0xffffffffu, s2, off, 16);
            s2 += 1e-8f;
            const float v = (sqrtf(s2) / (1.f + s2)) * acc;
            float l2 = v * v;
#pragma unroll
            for (int off = 8; off; off >>= 1) l2 += __shfl_xor_sync(0xffffffffu, l2, off, 16);
            if ((tid & 15) == 0) out[b * 2 + j] = sqrtf(l2 + 1e-8f);
        }
        __syncthreads();
        if (tid == 0) {   // reset per-batch counters for next graph replay
            d_cntF[b] = 0;
            d_cntS[b] = 0;
            d_cntA[b] = 0;
            d_cntB[b] = 0;
        }
    }
}

// ---------------------------------------------------------------------------
extern "C" void kernel_launch(void* const* d_in, const int* in_sizes, int n_in,
                              void* d_out, int out_size) {
    const float* x      = (const float*)d_in[0];
    const float* conv_w = (const float*)d_in[1];
    const float* conv_b = (const float*)d_in[2];
    const float* ca_w1  = (const float*)d_in[3];
    const float* ca_w2  = (const float*)d_in[4];
    const float* sa_w   = (const float*)d_in[5];
    const float* caps_W = (const float*)d_in[6];
    float* out = (float*)d_out;

    const int hs_bytes = CC * HSS * sizeof(__half);   // 61440
    cudaFuncSetAttribute(k_all, cudaFuncAttributeMaxDynamicSharedMemorySize, hs_bytes);

    k_all<<<dim3(NTF, BB), 256, hs_bytes>>>(x, conv_w, conv_b, sa_w,
                                            ca_w1, ca_w2, caps_W, out);
}

// round 16
// speedup vs baseline: 1.6551x; 1.0036x over previous
#include <cuda_runtime.h>
#include <cuda_fp16.h>
#include <cuda_fp8.h>
#include <math.h>

#define HH 134
#define WW 20
#define HW 2680
#define CC 64
#define BB 128
#define NIN 21440        // 8-elem groups per batch
#define NTF 8
#define RTF 18
#define NHALO 24         // RTF + 6
#define HSS 480          // NHALO * WW (halfs per channel in smem)

// ---- scratch (static device globals) ----
__device__ unsigned char d_u[(size_t)BB * CC * HW];  // u fp8 e4m3, 22 MB
__device__ float d_psum[NTF * BB * CC];
__device__ float d_pmax[NTF * BB * CC];
__device__ float d_pu[NTF * BB * 8];     // partials of S[k]
__device__ float d_pscA[NTF * BB * 8];
__device__ float d_pscB[NTF * BB * 8];
__device__ int d_cntF[BB], d_cntS[BB], d_cntB[BB];

// per-batch spin barrier (8 peer blocks)
__device__ __forceinline__ void batch_barrier(int* cnt, int b, int tid) {
    if (tid == 0) {
        __threadfence();
        atomicAdd(&cnt[b], 1);
        while (*((volatile int*)&cnt[b]) < 8) __nanosleep(64);
        __threadfence();
    }
    __syncthreads();
}

// routing update chain (warp 0): sc[16] -> s -> squash -> v -> g
__device__ __forceinline__ void upd_chain(const float* __restrict__ W,
                                          const float* sc, float* vs,
                                          float* g, bool add, int lane) {
    const int j = lane >> 4;
    float acc = 0.f;
#pragma unroll
    for (int k = 0; k < 8; k++) acc += sc[j * 8 + k] * W[k * 32 + lane];
    float s2 = acc * acc;
#pragma unroll
    for (int off = 8; off; off >>= 1) s2 += __shfl_xor_sync(0xffffffffu, s2, off, 16);
    s2 += 1e-8f;
    const float v = (sqrtf(s2) / (1.f + s2)) * acc;
    vs[lane] = v;
    __syncwarp();
    if (lane < 16) {
        const int jj = lane >> 3, k = lane & 7;
        float a = 0.f;
#pragma unroll
        for (int dd = 0; dd < 16; dd++) a += vs[jj * 16 + dd] * W[k * 32 + jj * 16 + dd];
        g[lane] = add ? (g[lane] + a) : a;
    }
    __syncwarp();
}

// ---------------------------------------------------------------------------
// K1: conv + CBAM + u(fp8 out) + routing PASS A from smem tile.
// grid (NTF, BB), 256 threads, dyn smem CC*HSS halfs = 60 KB, 3 blocks/SM.
// ---------------------------------------------------------------------------
__global__ void __launch_bounds__(256, 3)
k_fuseA(const float* __restrict__ x,
        const float* __restrict__ cw,
        const float* __restrict__ cb,
        const float* __restrict__ sw,
        const float* __restrict__ w1,
        const float* __restrict__ w2,
        const float* __restrict__ W) {
    extern __shared__ __half hs[];                // [CC][HSS] h, later u
    __shared__ __align__(16) float wsh[CC * 12];
    __shared__ float cbs[CC], cas[CC], ws[98];
    __shared__ float avg_s[CC], mx_s[CC], hid_s[8];
    __shared__ float xs[26 * WW];
    __shared__ float spm[NHALO * WW], spx[NHALO * WW];
    __shared__ float sa_s[RTF * WW];
    __shared__ float red[8][8];
    __shared__ float Ssh[8], sc[16], vs[32], g[16];

    const int tile = blockIdx.x, b = blockIdx.y, tid = threadIdx.x;
    const int warp = tid >> 5, lane = tid & 31;
    const int r0 = tile * RTF, nr = min(RTF, HH - r0);
    const int hs0 = max(r0 - 3, 0), hs1 = min(r0 + nr + 3, HH), nhs = hs1 - hs0;
    const int lx0 = max(hs0 - 1, 0), lx1 = min(hs1 + 1, HH), nlx = lx1 - lx0;

    for (int i = tid; i < CC * 12; i += 256) {
        const int c = i / 12, q = i - c * 12;
        wsh[i] = (q < 9) ? cw[c * 9 + q] : 0.f;
    }
    if (tid < CC) cbs[tid] = cb[tid];
    if (tid >= 64 && tid < 64 + 98) ws[tid - 64] = sw[tid - 64];
    for (int i = tid; i < nlx * WW; i += 256) xs[i] = x[(size_t)b * HW + lx0 * WW + i];
    __syncthreads();

    // ---- stage 1: conv (raw h) over halo rows -> hs ----
    {
        const int pairs = nhs * 10;
        if (tid < pairs) {
            const int lrow = tid / 10, col2 = (tid - lrow * 10) * 2;
            const int row = hs0 + lrow;
            float win[3][4];
#pragma unroll
            for (int r = 0; r < 3; r++) {
                const int ih = row - 1 + r;
                const bool vr = (ih >= lx0) && (ih < lx1);
                const int lr = ih - lx0;
#pragma unroll
                for (int q = 0; q < 4; q++) {
                    const int iw = col2 - 1 + q;
                    win[r][q] = (vr && (unsigned)iw < WW) ? xs[lr * WW + iw] : 0.f;
                }
            }
#pragma unroll 2
            for (int c = 0; c < CC; c++) {
                const float4 wa = *(const float4*)&wsh[c * 12];
                const float4 wb = *(const float4*)&wsh[c * 12 + 4];
                const float w8 = wsh[c * 12 + 8];
                const float bias = cbs[c];
                float h0 = bias + wa.x * win[0][0] + wa.y * win[0][1] + wa.z * win[0][2]
                                + wa.w * win[1][0] + wb.x * win[1][1] + wb.y * win[1][2]
                                + wb.z * win[2][0] + wb.w * win[2][1] + w8 * win[2][2];
                float h1 = bias + wa.x * win[0][1] + wa.y * win[0][2] + wa.z * win[0][3]
                                + wa.w * win[1][1] + wb.x * win[1][2] + wb.y * win[1][3]
                                + wb.z * win[2][1] + wb.w * win[2][2] + w8 * win[2][3];
                *(__half2*)&hs[c * HSS + lrow * WW + col2] =
                    __floats2half2_rn(fmaxf(h0, 0.f), fmaxf(h1, 0.f));
            }
        }
    }
    __syncthreads();

    // ---- stage 2: raw-h stats over OWN rows, partials -> global ----
    {
        const int tot2 = (nr * WW) >> 1;
        const int off2 = ((r0 - hs0) * WW) >> 1;
#pragma unroll
        for (int cc = 0; cc < 8; cc++) {
            const int c = warp * 8 + cc;
            const __half2* hrow = (const __half2*)(hs + c * HSS) + off2;
            float s = 0.f, m = 0.f;
            for (int j = lane; j < tot2; j += 32) {
                const float2 f = __half22float2(hrow[j]);
                s += f.x + f.y;
                m = fmaxf(m, fmaxf(f.x, f.y));
            }
#pragma unroll
            for (int off = 16; off; off >>= 1) {
                s += __shfl_down_sync(0xffffffffu, s, off);
                m = fmaxf(m, __shfl_down_sync(0xffffffffu, m, off));
            }
            if (lane == 0) {
                d_psum[(tile * BB + b) * CC + c] = s;
                d_pmax[(tile * BB + b) * CC + c] = m;
            }
        }
    }
    __syncthreads();

    // ---- stage 3: batch barrier, ca MLP ----
    batch_barrier(d_cntF, b, tid);
    if (tid < CC) {
        float s = 0.f, m = 0.f;
#pragma unroll
        for (int t = 0; t < NTF; t++) {
            s += d_psum[(t * BB + b) * CC + tid];
            m = fmaxf(m, d_pmax[(t * BB + b) * CC + tid]);
        }
        avg_s[tid] = s * (1.f / (float)HW);
        mx_s[tid] = m;
    }
    __syncthreads();
    if (tid < 8) {
        const int i = tid & 3;
        const float* v = (tid < 4) ? avg_s : mx_s;
        float a = 0.f;
        for (int c = 0; c < CC; c++) a += v[c] * w1[i * CC + c];
        hid_s[tid] = fmaxf(a, 0.f);
    }
    __syncthreads();
    if (tid < CC) {
        float o = 0.f;
#pragma unroll
        for (int i = 0; i < 4; i++) o += (hid_s[i] + hid_s[4 + i]) * w2[tid * 4 + i];
        cas[tid] = 1.f / (1.f + __expf(-o));
    }
    __syncthreads();

    // ---- stage 4: spm/spx over halo rows (ca folded) ----
    {
        const int pairs = nhs * 10;
        if (tid < pairs) {
            float s0 = 0.f, s1 = 0.f, m0 = -1e30f, m1 = -1e30f;
#pragma unroll 8
            for (int c = 0; c < CC; c++) {
                const float2 f = __half22float2(*(const __half2*)&hs[c * HSS + tid * 2]);
                const float cv = cas[c];
                const float ax = f.x * cv, ay = f.y * cv;
                s0 += ax; s1 += ay;
                m0 = fmaxf(m0, ax); m1 = fmaxf(m1, ay);
            }
            spm[tid * 2] = s0 * (1.f / (float)CC);
            spm[tid * 2 + 1] = s1 * (1.f / (float)CC);
            spx[tid * 2] = m0;
            spx[tid * 2 + 1] = m1;
        }
    }
    __syncthreads();

    // ---- stage 5: 7x7 -> sa; S partials ----
    float ps[8];
#pragma unroll
    for (int k = 0; k < 8; k++) ps[k] = 0.f;
    for (int p = tid; p < nr * WW; p += 256) {
        const int hh = r0 + p / WW, ww = p - (p / WW) * WW;
        float acc = 0.f;
#pragma unroll
        for (int kh = 0; kh < 7; kh++) {
            const int ih = hh + kh - 3;
            if ((unsigned)ih >= HH) continue;
            const int lrow = ih - hs0;
#pragma unroll
            for (int kw = 0; kw < 7; kw++) {
                const int iw = ww + kw - 3;
                if ((unsigned)iw >= WW) continue;
                const int q = lrow * WW + iw;
                acc += spm[q] * ws[kh * 7 + kw] + spx[q] * ws[49 + kh * 7 + kw];
            }
        }
        const float sa = 1.f / (1.f + __expf(-acc));
        sa_s[p] = sa;
        const int k = (r0 * WW + p) & 7;
        ps[k] += (float)CC * spm[(hh - hs0) * WW + ww] * sa;
    }
#pragma unroll
    for (int k = 0; k < 8; k++) {
#pragma unroll
        for (int off = 16; off; off >>= 1)
            ps[k] += __shfl_down_sync(0xffffffffu, ps[k], off);
    }
    if (lane == 0) {
#pragma unroll
        for (int k = 0; k < 8; k++) red[warp][k] = ps[k];
    }
    __syncthreads();
    if (tid < 8) {
        float s = 0.f;
#pragma unroll
        for (int w = 0; w < 8; w++) s += red[w][tid];
        d_pu[(tile * BB + b) * 8 + tid] = s;
    }

    // ---- stage 6: u = h*ca*sa IN PLACE + fp8 write (own rows) ----
    {
        const int tot2 = (nr * WW) >> 1;
        const int off2 = ((r0 - hs0) * WW) >> 1;
#pragma unroll
        for (int cc = 0; cc < 8; cc++) {
            const int c = warp * 8 + cc;
            const float cv = cas[c];
            __half2* row = (__half2*)(hs + c * HSS) + off2;
            unsigned short* urow =
                (unsigned short*)(d_u + (size_t)(b * CC + c) * HW + r0 * WW);
            for (int j = lane; j < tot2; j += 32) {
                const __half2 uv = __hmul2(row[j],
                    __floats2half2_rn(cv * sa_s[2 * j], cv * sa_s[2 * j + 1]));
                row[j] = uv;
                const float2 f = __half22float2(uv);
                urow[j] = (unsigned short)__nv_cvt_float2_to_fp8x2(
                    f, __NV_SATFINITE, __NV_E4M3);
            }
        }
    }
    __syncthreads();

    // ---- stage 7: S barrier -> g1 -> PASS A over own smem tile ----
    batch_barrier(d_cntS, b, tid);
    if (tid < 32) {
        if (tid < 8) {
            float S = 0.f;
#pragma unroll
            for (int t = 0; t < NTF; t++) S += d_pu[(t * BB + b) * 8 + tid];
            Ssh[tid] = S;
        }
        __syncwarp();
        if (tid < 16) sc[tid] = 0.5f * Ssh[tid & 7];
        __syncwarp();
        upd_chain(W, sc, vs, g, false, tid);   // g1
    }
    __syncthreads();

    float gd[8], a0[8];
#pragma unroll
    for (int k = 0; k < 8; k++) { gd[k] = g[k] - g[8 + k]; a0[k] = 0.f; }

    const int ngroups = (nr * WW) >> 3;
    const int uoff = (r0 - hs0) * WW;
    const int total = CC * ngroups;
    for (int idx = tid; idx < total; idx += 256) {
        const int c = idx / ngroups, gp = idx - c * ngroups;
        const __half* up = hs + c * HSS + uoff + gp * 8;
        const uint2 ra = *(const uint2*)up;
        const uint2 rb = *(const uint2*)(up + 4);
        float u[8];
        float2 f;
        f = __half22float2(*(const __half2*)&ra.x); u[0] = f.x; u[1] = f.y;
        f = __half22float2(*(const __half2*)&ra.y); u[2] = f.x; u[3] = f.y;
        f = __half22float2(*(const __half2*)&rb.x); u[4] = f.x; u[5] = f.y;
        f = __half22float2(*(const __half2*)&rb.y); u[6] = f.x; u[7] = f.y;
        float d = 0.f;
#pragma unroll
        for (int k = 0; k < 8; k++) d += u[k] * gd[k];
        const float c0 = 1.f / (1.f + __expf(-d));
#pragma unroll
        for (int k = 0; k < 8; k++) a0[k] += c0 * u[k];
    }
#pragma unroll
    for (int k = 0; k < 8; k++) {
#pragma unroll
        for (int off = 16; off; off >>= 1)
            a0[k] += __shfl_down_sync(0xffffffffu, a0[k], off);
    }
    if (lane == 0) {
#pragma unroll
        for (int k = 0; k < 8; k++) red[warp][k] = a0[k];
    }
    __syncthreads();
    if (tid < 8) {
        float s = 0.f;
#pragma unroll
        for (int w = 0; w < 8; w++) s += red[w][tid];
        d_pscA[(tile * BB + b) * 8 + tid] = s;
    }
}

// ---------------------------------------------------------------------------
// K2: g2 from pscA, ONE fp8 global pass (pass B), pscB, per-batch final.
// grid (8, BB), 256 threads.
// ---------------------------------------------------------------------------
__global__ void k_routeB(const float* __restrict__ W, float* __restrict__ out) {
    __shared__ float Ssh[8], ash[8], sc[16], vs[32], g[16];
    __shared__ float red[8][8];
    __shared__ int lastflag;
    const int chunk = blockIdx.x, b = blockIdx.y, tid = threadIdx.x;
    const int warp = tid >> 5, lane = tid & 31;

    // g2 = g1(S) + dW(pscA)   (kernel boundary guarantees pscA complete)
    if (tid < 32) {
        if (tid < 8) {
            float S = 0.f, a = 0.f;
#pragma unroll
            for (int t = 0; t < NTF; t++) {
                S += d_pu[(t * BB + b) * 8 + tid];
                a += d_pscA[(t * BB + b) * 8 + tid];
            }
            Ssh[tid] = S;
            ash[tid] = a;
        }
        __syncwarp();
        if (tid < 16) sc[tid] = 0.5f * Ssh[tid & 7];
        __syncwarp();
        upd_chain(W, sc, vs, g, false, tid);   // g1
        if (tid < 16) sc[tid] = (tid < 8) ? ash[tid] : (Ssh[tid - 8] - ash[tid - 8]);
        __syncwarp();
        upd_chain(W, sc, vs, g, true, tid);    // g2
    }
    __syncthreads();

    float gd[8], a0[8];
#pragma unroll
    for (int k = 0; k < 8; k++) { gd[k] = g[k] - g[8 + k]; a0[k] = 0.f; }

    const uint4* up4 = (const uint4*)(d_u + (size_t)b * CC * HW + (size_t)chunk * (NIN / 8) * 8);
    const int npair = NIN / 16;

    auto comp = [&](const uint4& raw) {
        const unsigned v[4] = {raw.x, raw.y, raw.z, raw.w};
        float u[16];
#pragma unroll
        for (int q = 0; q < 4; q++) {
            const __half2_raw hr0 = __nv_cvt_fp8x2_to_halfraw2(
                (__nv_fp8x2_storage_t)(v[q] & 0xffffu), __NV_E4M3);
            const __half2_raw hr1 = __nv_cvt_fp8x2_to_halfraw2(
                (__nv_fp8x2_storage_t)(v[q] >> 16), __NV_E4M3);
            const float2 f0 = __half22float2(__half2(hr0));
            const float2 f1 = __half22float2(__half2(hr1));
            u[q * 4 + 0] = f0.x; u[q * 4 + 1] = f0.y;
            u[q * 4 + 2] = f1.x; u[q * 4 + 3] = f1.y;
        }
        float d0 = 0.f, d1 = 0.f;
#pragma unroll
        for (int k = 0; k < 8; k++) { d0 += u[k] * gd[k]; d1 += u[8 + k] * gd[k]; }
        const float c0a = 1.f / (1.f + __expf(-d0));
        const float c0b = 1.f / (1.f + __expf(-d1));
#pragma unroll
        for (int k = 0; k < 8; k++) a0[k] += c0a * u[k] + c0b * u[8 + k];
    };

    int i = tid;
    for (; i + 768 < npair; i += 1024) {
        const uint4 r0 = up4[i];
        const uint4 r1 = up4[i + 256];
        const uint4 r2 = up4[i + 512];
        const uint4 r3 = up4[i + 768];
        comp(r0); comp(r1); comp(r2); comp(r3);
    }
    for (; i < npair; i += 256) {
        const uint4 r0 = up4[i];
        comp(r0);
    }

#pragma unroll
    for (int k = 0; k < 8; k++) {
#pragma unroll
        for (int off = 16; off; off >>= 1)
            a0[k] += __shfl_down_sync(0xffffffffu, a0[k], off);
    }
    if (lane == 0) {
#pragma unroll
        for (int k = 0; k < 8; k++) red[warp][k] = a0[k];
    }
    __syncthreads();
    if (tid < 8) {
        float s = 0.f;
#pragma unroll
        for (int w = 0; w < 8; w++) s += red[w][tid];
        d_pscB[(chunk * BB + b) * 8 + tid] = s;
    }
    __syncthreads();

    // per-batch last block: final lengths + counter resets
    if (tid == 0) {
        __threadfence();
        lastflag = (atomicAdd(&d_cntB[b], 1) == 7) ? 1 : 0;
    }
    __syncthreads();
    if (lastflag) {
        if (tid < 32) {
            __threadfence();
            if (tid < 8) {
                float a = 0.f;
#pragma unroll
                for (int ch = 0; ch < 8; ch++) a += d_pscB[(ch * BB + b) * 8 + tid];
                ash[tid] = a;
            }
            __syncwarp();
            if (tid < 16) sc[tid] = (tid < 8) ? ash[tid] : (Ssh[tid - 8] - ash[tid - 8]);
            __syncwarp();
            const int j = tid >> 4;
            float acc = 0.f;
#pragma unroll
            for (int k = 0; k < 8; k++) acc += sc[j * 8 + k] * W[k * 32 + tid];
            float s2 = acc * acc;
#pragma unroll
            for (int off = 8; off; off >>= 1) s2 += __shfl_xor_sync(0xffffffffu, s2, off, 16);
            s2 += 1e-8f;
            const float v = (sqrtf(s2) / (1.f + s2)) * acc;
            float l2 = v * v;
#pragma unroll
            for (int off = 8; off; off >>= 1) l2 += __shfl_xor_sync(0xffffffffu, l2, off, 16);
            if ((tid & 15) == 0) out[b * 2 + j] = sqrtf(l2 + 1e-8f);
        }
        __syncthreads();
        if (tid == 0) {   // reset per-batch counters for next graph replay
            d_cntF[b] = 0;
            d_cntS[b] = 0;
            d_cntB[b] = 0;
        }
    }
}

// ---------------------------------------------------------------------------
extern "C" void kernel_launch(void* const* d_in, const int* in_sizes, int n_in,
                              void* d_out, int out_size) {
    const float* x      = (const float*)d_in[0];
    const float* conv_w = (const float*)d_in[1];
    const float* conv_b = (const float*)d_in[2];
    const float* ca_w1  = (const float*)d_in[3];
    const float* ca_w2  = (const float*)d_in[4];
    const float* sa_w   = (const float*)d_in[5];
    const float* caps_W = (const float*)d_in[6];
    float* out = (float*)d_out;

    const int hs_bytes = CC * HSS * sizeof(__half);   // 61440
    cudaFuncSetAttribute(k_fuseA, cudaFuncAttributeMaxDynamicSharedMemorySize, hs_bytes);

    k_fuseA<<<dim3(NTF, BB), 256, hs_bytes>>>(x, conv_w, conv_b, sa_w,
                                              ca_w1, ca_w2, caps_W);
    k_routeB<<<dim3(8, BB), 256>>>(caps_W, out);
}

// round 17
// speedup vs baseline: 2.0172x; 1.2188x over previous
#include <cuda_runtime.h>
#include <cuda_fp16.h>
#include <cuda_fp8.h>
#include <math.h>

#define HH 134
#define WW 20
#define HW 2680
#define CC 64
#define BB 128
#define NIN 21440        // 8-elem groups per batch
#define NTF 8
#define RTF 17
#define NHALO 23         // RTF + 6
#define HSS 460          // NHALO * WW

// ---- scratch (static device globals) ----
__device__ unsigned char d_u[(size_t)BB * CC * HW];  // u fp8 e4m3, 22 MB
__device__ float d_psum[NTF * BB * CC];
__device__ float d_pmax[NTF * BB * CC];
__device__ float d_pu[NTF * BB * 8];
__device__ float d_pscA[8 * BB * 8];
__device__ float d_pscB[8 * BB * 8];
__device__ int d_cntF[BB];   // fuse stats barrier
__device__ int d_cntA[BB];   // route pass-A barrier
__device__ int d_cntB[BB];   // route pass-B / final

// per-batch spin barrier among 8 peer blocks
__device__ __forceinline__ void batch_barrier(int* cnt, int b, int tid) {
    if (tid == 0) {
        __threadfence();
        atomicAdd(&cnt[b], 1);
        while (*((volatile int*)&cnt[b]) < 8) __nanosleep(64);
        __threadfence();
    }
    __syncthreads();
}

// routing update chain (warp 0): sc[16] -> s -> squash -> v -> g
__device__ __forceinline__ void upd_chain(const float* __restrict__ W,
                                          const float* sc, float* vs,
                                          float* g, bool add, int lane) {
    const int j = lane >> 4;
    float acc = 0.f;
#pragma unroll
    for (int k = 0; k < 8; k++) acc += sc[j * 8 + k] * W[k * 32 + lane];
    float s2 = acc * acc;
#pragma unroll
    for (int off = 8; off; off >>= 1) s2 += __shfl_xor_sync(0xffffffffu, s2, off, 16);
    s2 += 1e-8f;
    const float v = (sqrtf(s2) / (1.f + s2)) * acc;
    vs[lane] = v;
    __syncwarp();
    if (lane < 16) {
        const int jj = lane >> 3, k = lane & 7;
        float a = 0.f;
#pragma unroll
        for (int dd = 0; dd < 16; dd++) a += vs[jj * 16 + dd] * W[k * 32 + jj * 16 + dd];
        g[lane] = add ? (g[lane] + a) : a;
    }
    __syncwarp();
}

// ---------------------------------------------------------------------------
// K1: conv(once, halo tiles) + stats + per-batch sync + ca + spatial attn + u.
// grid (NTF, BB), 256 threads, dyn smem CC*HSS halfs = 57.5 KB. (round-11 exact)
// ---------------------------------------------------------------------------
__global__ void k_fuse_all(const float* __restrict__ x,
                           const float* __restrict__ cw,
                           const float* __restrict__ cb,
                           const float* __restrict__ sw,
                           const float* __restrict__ w1,
                           const float* __restrict__ w2) {
    extern __shared__ __half hs[];                // [CC][HSS] raw h fp16
    __shared__ __align__(16) float wsh[CC * 12];
    __shared__ float cbs[CC], cas[CC], ws[98];
    __shared__ float avg_s[CC], mx_s[CC], hid_s[8];
    __shared__ float xs[25 * WW];
    __shared__ float spm[NHALO * WW], spx[NHALO * WW];
    __shared__ float sa_s[RTF * WW];
    __shared__ float red[8][8];

    const int tile = blockIdx.x, b = blockIdx.y, tid = threadIdx.x;
    const int warp = tid >> 5, lane = tid & 31;
    const int r0 = tile * RTF, nr = min(RTF, HH - r0);
    const int hs0 = max(r0 - 3, 0), hs1 = min(r0 + nr + 3, HH), nhs = hs1 - hs0;
    const int lx0 = max(hs0 - 1, 0), lx1 = min(hs1 + 1, HH), nlx = lx1 - lx0;

    for (int i = tid; i < CC * 12; i += 256) {
        const int c = i / 12, q = i - c * 12;
        wsh[i] = (q < 9) ? cw[c * 9 + q] : 0.f;
    }
    if (tid < CC) cbs[tid] = cb[tid];
    if (tid >= 64 && tid < 64 + 98) ws[tid - 64] = sw[tid - 64];
    for (int i = tid; i < nlx * WW; i += 256) xs[i] = x[(size_t)b * HW + lx0 * WW + i];
    __syncthreads();

    // stage 1: conv RAW over halo rows -> hs
    {
        const int pairs = nhs * 10;
        if (tid < pairs) {
            const int lrow = tid / 10, col2 = (tid - lrow * 10) * 2;
            const int row = hs0 + lrow;
            float win[3][4];
#pragma unroll
            for (int r = 0; r < 3; r++) {
                const int ih = row - 1 + r;
                const bool vr = (ih >= lx0) && (ih < lx1);
                const int lr = ih - lx0;
#pragma unroll
                for (int q = 0; q < 4; q++) {
                    const int iw = col2 - 1 + q;
                    win[r][q] = (vr && (unsigned)iw < WW) ? xs[lr * WW + iw] : 0.f;
                }
            }
#pragma unroll 4
            for (int c = 0; c < CC; c++) {
                const float4 wa = *(const float4*)&wsh[c * 12];
                const float4 wb = *(const float4*)&wsh[c * 12 + 4];
                const float w8 = wsh[c * 12 + 8];
                const float bias = cbs[c];
                float h0 = bias + wa.x * win[0][0] + wa.y * win[0][1] + wa.z * win[0][2]
                                + wa.w * win[1][0] + wb.x * win[1][1] + wb.y * win[1][2]
                                + wb.z * win[2][0] + wb.w * win[2][1] + w8 * win[2][2];
                float h1 = bias + wa.x * win[0][1] + wa.y * win[0][2] + wa.z * win[0][3]
                                + wa.w * win[1][1] + wb.x * win[1][2] + wb.y * win[1][3]
                                + wb.z * win[2][1] + wb.w * win[2][2] + w8 * win[2][3];
                *(__half2*)&hs[c * HSS + lrow * WW + col2] =
                    __floats2half2_rn(fmaxf(h0, 0.f), fmaxf(h1, 0.f));
            }
        }
    }
    __syncthreads();

    // stage 2: raw-h stats over OWN rows (warp-per-channel), write partials
    {
        const int tot2 = (nr * WW) >> 1;
        const int off2 = ((r0 - hs0) * WW) >> 1;
#pragma unroll
        for (int cc = 0; cc < 8; cc++) {
            const int c = warp * 8 + cc;
            const __half2* hrow = (const __half2*)(hs + c * HSS) + off2;
            float s = 0.f, m = 0.f;
            for (int j = lane; j < tot2; j += 32) {
                const float2 f = __half22float2(hrow[j]);
                s += f.x + f.y;
                m = fmaxf(m, fmaxf(f.x, f.y));
            }
#pragma unroll
            for (int off = 16; off; off >>= 1) {
                s += __shfl_down_sync(0xffffffffu, s, off);
                m = fmaxf(m, __shfl_down_sync(0xffffffffu, m, off));
            }
            if (lane == 0) {
                d_psum[(tile * BB + b) * CC + c] = s;
                d_pmax[(tile * BB + b) * CC + c] = m;
            }
        }
    }
    __syncthreads();

    // stage 3: per-batch barrier, then ca MLP
    batch_barrier(d_cntF, b, tid);
    if (tid < CC) {
        float s = 0.f, m = 0.f;
#pragma unroll
        for (int t = 0; t < NTF; t++) {
            s += d_psum[(t * BB + b) * CC + tid];
            m = fmaxf(m, d_pmax[(t * BB + b) * CC + tid]);
        }
        avg_s[tid] = s * (1.f / (float)HW);
        mx_s[tid] = m;
    }
    __syncthreads();
    if (tid < 8) {
        const int i = tid & 3;
        const float* v = (tid < 4) ? avg_s : mx_s;
        float a = 0.f;
        for (int c = 0; c < CC; c++) a += v[c] * w1[i * CC + c];
        hid_s[tid] = fmaxf(a, 0.f);
    }
    __syncthreads();
    if (tid < CC) {
        float o = 0.f;
#pragma unroll
        for (int i = 0; i < 4; i++) o += (hid_s[i] + hid_s[4 + i]) * w2[tid * 4 + i];
        cas[tid] = 1.f / (1.f + __expf(-o));
    }
    __syncthreads();

    // stage 4: spm/spx over halo rows (ca folded in scan)
    {
        const int pairs = nhs * 10;
        if (tid < pairs) {
            float s0 = 0.f, s1 = 0.f, m0 = -1e30f, m1 = -1e30f;
#pragma unroll 8
            for (int c = 0; c < CC; c++) {
                const float2 f = __half22float2(*(const __half2*)&hs[c * HSS + tid * 2]);
                const float cv = cas[c];
                const float ax = f.x * cv, ay = f.y * cv;
                s0 += ax; s1 += ay;
                m0 = fmaxf(m0, ax); m1 = fmaxf(m1, ay);
            }
            spm[tid * 2] = s0 * (1.f / (float)CC);
            spm[tid * 2 + 1] = s1 * (1.f / (float)CC);
            spx[tid * 2] = m0;
            spx[tid * 2 + 1] = m1;
        }
    }
    __syncthreads();

    // stage 5: 7x7 conv -> sa; S partials
    float ps[8];
#pragma unroll
    for (int k = 0; k < 8; k++) ps[k] = 0.f;
    for (int p = tid; p < nr * WW; p += 256) {
        const int hh = r0 + p / WW, ww = p - (p / WW) * WW;
        float acc = 0.f;
#pragma unroll
        for (int kh = 0; kh < 7; kh++) {
            const int ih = hh + kh - 3;
            if ((unsigned)ih >= HH) continue;
            const int lrow = ih - hs0;
#pragma unroll
            for (int kw = 0; kw < 7; kw++) {
                const int iw = ww + kw - 3;
                if ((unsigned)iw >= WW) continue;
                const int q = lrow * WW + iw;
                acc += spm[q] * ws[kh * 7 + kw] + spx[q] * ws[49 + kh * 7 + kw];
            }
        }
        const float sa = 1.f / (1.f + __expf(-acc));
        sa_s[p] = sa;
        const int k = (r0 * WW + p) & 7;
        ps[k] += (float)CC * spm[(hh - hs0) * WW + ww] * sa;
    }
#pragma unroll
    for (int k = 0; k < 8; k++) {
#pragma unroll
        for (int off = 16; off; off >>= 1)
            ps[k] += __shfl_down_sync(0xffffffffu, ps[k], off);
    }
    if (lane == 0) {
#pragma unroll
        for (int k = 0; k < 8; k++) red[warp][k] = ps[k];
    }
    __syncthreads();
    if (tid < 8) {
        float s = 0.f;
#pragma unroll
        for (int w = 0; w < 8; w++) s += red[w][tid];
        d_pu[(tile * BB + b) * 8 + tid] = s;
    }

    // stage 6: u = h*ca*sa -> fp8, warp-per-channel coalesced
    {
        const int tot4 = (nr * WW) >> 2;
        const int off2 = ((r0 - hs0) * WW) >> 1;
#pragma unroll
        for (int cc = 0; cc < 8; cc++) {
            const int c = warp * 8 + cc;
            const float cv = cas[c];
            const __half2* hrow = (const __half2*)(hs + c * HSS) + off2;
            unsigned* urow = (unsigned*)(d_u + (size_t)(b * CC + c) * HW + r0 * WW);
            for (int j = lane; j < tot4; j += 32) {
                const float2 fa = __half22float2(hrow[2 * j]);
                const float2 fb = __half22float2(hrow[2 * j + 1]);
                float2 q0, q1;
                q0.x = fa.x * (cv * sa_s[4 * j]);
                q0.y = fa.y * (cv * sa_s[4 * j + 1]);
                q1.x = fb.x * (cv * sa_s[4 * j + 2]);
                q1.y = fb.y * (cv * sa_s[4 * j + 3]);
                const unsigned lo = __nv_cvt_float2_to_fp8x2(q0, __NV_SATFINITE, __NV_E4M3);
                const unsigned hi = __nv_cvt_float2_to_fp8x2(q1, __NV_SATFINITE, __NV_E4M3);
                urow[j] = (hi << 16) | lo;
            }
        }
    }
}

// ---------------------------------------------------------------------------
// K2: BOTH routing passes + final, per-batch barriers. grid (8, BB), 256.
// MLP-8 front-batched streaming (uncapped regs).
// ---------------------------------------------------------------------------
__global__ void k_route_all(const float* __restrict__ W, float* __restrict__ out) {
    __shared__ float Ssh[8], ash[8], sc[16], vs[32], g[16];
    __shared__ float red[8][8];
    __shared__ int lastflag;
    const int chunk = blockIdx.x, b = blockIdx.y, tid = threadIdx.x;
    const int warp = tid >> 5, lane = tid & 31;

    // g1 from S
    if (tid < 32) {
        if (tid < 8) {
            float S = 0.f;
#pragma unroll
            for (int t = 0; t < NTF; t++) S += d_pu[(t * BB + b) * 8 + tid];
            Ssh[tid] = S;
        }
        __syncwarp();
        if (tid < 16) sc[tid] = 0.5f * Ssh[tid & 7];
        __syncwarp();
        upd_chain(W, sc, vs, g, false, tid);
    }
    __syncthreads();

    const uint4* up4 = (const uint4*)(d_u + (size_t)b * CC * HW + (size_t)chunk * (NIN / 8) * 8);
    const int npair = NIN / 16;    // 1340 16B loads per chunk, 5.24/thread

    float gd[8], a0[8];

    auto stream_pass = [&]() {
#pragma unroll
        for (int k = 0; k < 8; k++) a0[k] = 0.f;
        auto comp = [&](const uint4& raw) {
            const unsigned v[4] = {raw.x, raw.y, raw.z, raw.w};
            float u[16];
#pragma unroll
            for (int q = 0; q < 4; q++) {
                const __half2_raw hr0 = __nv_cvt_fp8x2_to_halfraw2(
                    (__nv_fp8x2_storage_t)(v[q] & 0xffffu), __NV_E4M3);
                const __half2_raw hr1 = __nv_cvt_fp8x2_to_halfraw2(
                    (__nv_fp8x2_storage_t)(v[q] >> 16), __NV_E4M3);
                const float2 f0 = __half22float2(__half2(hr0));
                const float2 f1 = __half22float2(__half2(hr1));
                u[q * 4 + 0] = f0.x; u[q * 4 + 1] = f0.y;
                u[q * 4 + 2] = f1.x; u[q * 4 + 3] = f1.y;
            }
            float d0 = 0.f, d1 = 0.f;
#pragma unroll
            for (int k = 0; k < 8; k++) { d0 += u[k] * gd[k]; d1 += u[8 + k] * gd[k]; }
            const float c0a = 1.f / (1.f + __expf(-d0));
            const float c0b = 1.f / (1.f + __expf(-d1));
#pragma unroll
            for (int k = 0; k < 8; k++) a0[k] += c0a * u[k] + c0b * u[8 + k];
        };
        // 5-deep front-batched (covers 5 of 5.24 iters in one batch)
        int i = tid;
        if (i + 1024 < npair) {
            uint4 r[5];
#pragma unroll
            for (int q = 0; q < 5; q++) r[q] = up4[i + q * 256];
#pragma unroll
            for (int q = 0; q < 5; q++) comp(r[q]);
            i += 5 * 256;
        }
        for (; i < npair; i += 256) {
            const uint4 r0 = up4[i];
            comp(r0);
        }
#pragma unroll
        for (int k = 0; k < 8; k++) {
#pragma unroll
            for (int off = 16; off; off >>= 1)
                a0[k] += __shfl_down_sync(0xffffffffu, a0[k], off);
        }
        if (lane == 0) {
#pragma unroll
            for (int k = 0; k < 8; k++) red[warp][k] = a0[k];
        }
        __syncthreads();
    };

    // ---- pass A ----
#pragma unroll
    for (int k = 0; k < 8; k++) gd[k] = g[k] - g[8 + k];
    stream_pass();
    if (tid < 8) {
        float s = 0.f;
#pragma unroll
        for (int w = 0; w < 8; w++) s += red[w][tid];
        d_pscA[(chunk * BB + b) * 8 + tid] = s;
    }
    __syncthreads();
    batch_barrier(d_cntA, b, tid);

    // g2 = g1 + dW(pscA)
    if (tid < 32) {
        if (tid < 8) {
            float a = 0.f;
#pragma unroll
            for (int ch = 0; ch < 8; ch++) a += d_pscA[(ch * BB + b) * 8 + tid];
            ash[tid] = a;
        }
        __syncwarp();
        if (tid < 16) sc[tid] = (tid < 8) ? ash[tid] : (Ssh[tid - 8] - ash[tid - 8]);
        __syncwarp();
        upd_chain(W, sc, vs, g, true, tid);
    }
    __syncthreads();

    // ---- pass B ----
#pragma unroll
    for (int k = 0; k < 8; k++) gd[k] = g[k] - g[8 + k];
    stream_pass();
    if (tid < 8) {
        float s = 0.f;
#pragma unroll
        for (int w = 0; w < 8; w++) s += red[w][tid];
        d_pscB[(chunk * BB + b) * 8 + tid] = s;
    }
    __syncthreads();

    // last block of this batch computes final lengths + resets counters
    if (tid == 0) {
        __threadfence();
        lastflag = (atomicAdd(&d_cntB[b], 1) == 7) ? 1 : 0;
    }
    __syncthreads();
    if (lastflag) {
        if (tid < 32) {
            __threadfence();
            if (tid < 8) {
                float a = 0.f;
#pragma unroll
                for (int ch = 0; ch < 8; ch++) a += d_pscB[(ch * BB + b) * 8 + tid];
                ash[tid] = a;
            }
            __syncwarp();
            if (tid < 16) sc[tid] = (tid < 8) ? ash[tid] : (Ssh[tid - 8] - ash[tid - 8]);
            __syncwarp();
            const int j = tid >> 4;
            float acc = 0.f;
#pragma unroll
            for (int k = 0; k < 8; k++) acc += sc[j * 8 + k] * W[k * 32 + tid];
            float s2 = acc * acc;
#pragma unroll
            for (int off = 8; off; off >>= 1) s2 += __shfl_xor_sync(0xffffffffu, s2, off, 16);
            s2 += 1e-8f;
            const float v = (sqrtf(s2) / (1.f + s2)) * acc;
            float l2 = v * v;
#pragma unroll
            for (int off = 8; off; off >>= 1) l2 += __shfl_xor_sync(0xffffffffu, l2, off, 16);
            if ((tid & 15) == 0) out[b * 2 + j] = sqrtf(l2 + 1e-8f);
        }
        __syncthreads();
        if (tid == 0) {   // reset per-batch counters for next graph replay
            d_cntF[b] = 0;
            d_cntA[b] = 0;
            d_cntB[b] = 0;
        }
    }
}

// ---------------------------------------------------------------------------
extern "C" void kernel_launch(void* const* d_in, const int* in_sizes, int n_in,
                              void* d_out, int out_size) {
    const float* x      = (const float*)d_in[0];
    const float* conv_w = (const float*)d_in[1];
    const float* conv_b = (const float*)d_in[2];
    const float* ca_w1  = (const float*)d_in[3];
    const float* ca_w2  = (const float*)d_in[4];
    const float* sa_w   = (const float*)d_in[5];
    const float* caps_W = (const float*)d_in[6];
    float* out = (float*)d_out;

    const int hs_bytes = CC * HSS * sizeof(__half);   // 58880
    cudaFuncSetAttribute(k_fuse_all, cudaFuncAttributeMaxDynamicSharedMemorySize, hs_bytes);

    k_fuse_all<<<dim3(NTF, BB), 256, hs_bytes>>>(x, conv_w, conv_b, sa_w, ca_w1, ca_w2);
    k_route_all<<<dim3(8, BB), 256>>>(caps_W, out);
}